// round 4
// baseline (speedup 1.0000x reference)
#include <cuda_runtime.h>
#include <math.h>
#include <stdint.h>

// Problem dims
#define BB   64
#define TT   512
#define DD   256
#define HH   1024
#define LL   256
#define OO   256
#define KC   32          // K chunk
#define NCH  48          // 1536 / 32
#define GRID 128
#define BLK  256

// Persistent state (no allocations allowed)
__device__ float g_h[2][BB*HH];   // double-buffered hidden state, [b][u] layout
__device__ float g_c[BB*HH];      // cell state, [u][b] layout (CTA-private by u-range)
__device__ float g_s[BB*LL];      // latent state, [b][l] layout
__device__ unsigned g_count;      // grid barrier counter

__global__ void reset_kernel() {
    int i = blockIdx.x * blockDim.x + threadIdx.x;
    if (i == 0) g_count = 0u;
    if (i < BB*HH) { g_h[0][i] = 0.f; g_c[i] = 0.f; }
    if (i < BB*LL) g_s[i] = 0.f;
}

__device__ __forceinline__ float sigm(float x) { return 1.f / (1.f + expf(-x)); }

// Grid barrier: release = fence-all-threads + arrive; acquire = spin + syncthreads.
__device__ __forceinline__ void gridbar(unsigned target) {
    __threadfence();
    __syncthreads();
    if (threadIdx.x == 0) {
        atomicAdd(&g_count, 1u);
        while (*((volatile unsigned*)&g_count) < target) { __nanosleep(64); }
    }
    __syncthreads();
    __threadfence();
}

__device__ __forceinline__ float dot4(float4 w, float4 v, float a) {
    a = fmaf(w.x, v.x, a);
    a = fmaf(w.y, v.y, a);
    a = fmaf(w.z, v.z, a);
    a = fmaf(w.w, v.w, a);
    return a;
}

// Shared arena (floats):
//   sW: [32 rows][32 k]  row-major, 16B-group XOR swizzle: group = kg ^ (row>>2)
//   sI: [64 b  ][32 k]  row-major, 16B-group XOR swizzle: group = kg ^ (b&7)
//   sG: [32 rows][65]   aliases arena front (used after the K loop)
#define SMEM_FLOATS (32*32 + 64*32)   // 3072 floats = 12 KB
#define SG_STRIDE 65

__global__ void __launch_bounds__(BLK)
lstm_persistent(
    const float* __restrict__ x,
    const float* __restrict__ Wih,  const float* __restrict__ Whh,
    const float* __restrict__ bih,  const float* __restrict__ bhh,
    const float* __restrict__ Wenc, const float* __restrict__ benc,
    const float* __restrict__ Wpred,const float* __restrict__ bpred,
    const float* __restrict__ Wact, const float* __restrict__ bact,
    float* __restrict__ out)
{
    __shared__ float sm[SMEM_FLOATS];
    float* sW = sm;            // 1024 floats
    float* sI = sm + 1024;     // 2048 floats
    float* sG = sm;            // 32*65 = 2080 floats (alias, after compute)

    const int tid  = threadIdx.x;
    const int lane = tid & 31;
    const int warp = tid >> 5;
    const int u0   = blockIdx.x * 8;   // 8 hidden units per CTA
    const int tj   = tid & 7;          // 8 row-groups of 4 rows
    const int tb   = tid >> 3;         // 32 batch-groups of 2 batches

    // Prefetch descriptors (constant over t)
    const int pw_row = tid >> 3;                 // 0..31 (gate-row within CTA tile)
    const int pw_kq  = (tid & 7) * 4;            // k offset of the float4
    const int pw_j   = ((pw_row >> 3) << 10) + u0 + (pw_row & 7);  // global gate row
    const int pi_b   = tid >> 2;                 // 0..63
    const int pi_ko  = (tid & 3) * 8;            // 8 floats (2 float4) per thread

    float* outY = out;
    float* outS = out + (size_t)BB * TT * OO;
    float* outP = out + (size_t)2 * BB * TT * OO;

    unsigned bt = 0;

    for (int t = 0; t < TT; ++t) {
        const float* hread  = g_h[t & 1];
        float*       hwrite = g_h[(t & 1) ^ 1];

        // ---------------- Phase A: gates GEMM [32 rows x 64 b], K=1536 ------
        float acc[4][2] = {{0.f,0.f},{0.f,0.f},{0.f,0.f},{0.f,0.f}};
        float4 wreg, ireg0, ireg1;

        // prefetch chunk 0 (k < 32: W from Wih, inp from x)
        {
            wreg = *(const float4*)(Wih + (size_t)pw_j * 512 + pw_kq);
            const float* xs = x + ((size_t)pi_b * TT + t) * DD + pi_ko;
            ireg0 = *(const float4*)xs;
            ireg1 = *(const float4*)(xs + 4);
        }

        for (int c = 0; c < NCH; ++c) {
            __syncthreads();   // previous compute done, smem free
            // store staged regs (row-major + XOR swizzle, no transpose)
            *(float4*)&sW[pw_row * 32 + 4 * ((pw_kq >> 2) ^ (pw_row >> 2))] = wreg;
            {
                int b7  = pi_b & 7;
                int kg2 = pi_ko >> 2;
                *(float4*)&sI[pi_b * 32 + 4 * ( kg2      ^ b7)] = ireg0;
                *(float4*)&sI[pi_b * 32 + 4 * ((kg2 + 1) ^ b7)] = ireg1;
            }
            __syncthreads();
            if (c + 1 < NCH) {   // overlap next chunk's LDG with compute
                int k0 = (c + 1) * KC;
                int k  = k0 + pw_kq;
                const float* wsrc = (k < 512) ? (Wih + (size_t)pw_j * 512 + k)
                                              : (Whh + (size_t)pw_j * 1024 + (k - 512));
                wreg = *(const float4*)wsrc;
                int ki = k0 + pi_ko;
                if (ki < 256) {
                    const float* p = x + ((size_t)pi_b * TT + t) * DD + ki;
                    ireg0 = *(const float4*)p;
                    ireg1 = *(const float4*)(p + 4);
                } else if (ki < 512) {
                    const float4* p = (const float4*)(g_s + pi_b * LL + (ki - 256));
                    ireg0 = __ldcg(p);
                    ireg1 = __ldcg(p + 1);
                } else {
                    const float4* p = (const float4*)(hread + pi_b * HH + (ki - 512));
                    ireg0 = __ldcg(p);
                    ireg1 = __ldcg(p + 1);
                }
            }
            // compute: 8 k-groups x (6 LDS.128 + 32 FFMA)
#pragma unroll
            for (int kg = 0; kg < 8; ++kg) {
                const int wg = 4 * (kg ^ tj);
                float4 w0 = *(const float4*)&sW[(4*tj + 0) * 32 + wg];
                float4 w1 = *(const float4*)&sW[(4*tj + 1) * 32 + wg];
                float4 w2 = *(const float4*)&sW[(4*tj + 2) * 32 + wg];
                float4 w3 = *(const float4*)&sW[(4*tj + 3) * 32 + wg];
                const int b0 = 2 * tb, b1 = 2 * tb + 1;
                float4 i0 = *(const float4*)&sI[b0 * 32 + 4 * (kg ^ (b0 & 7))];
                float4 i1 = *(const float4*)&sI[b1 * 32 + 4 * (kg ^ (b1 & 7))];
                acc[0][0] = dot4(w0, i0, acc[0][0]);
                acc[0][1] = dot4(w0, i1, acc[0][1]);
                acc[1][0] = dot4(w1, i0, acc[1][0]);
                acc[1][1] = dot4(w1, i1, acc[1][1]);
                acc[2][0] = dot4(w2, i0, acc[2][0]);
                acc[2][1] = dot4(w2, i1, acc[2][1]);
                acc[3][0] = dot4(w3, i0, acc[3][0]);
                acc[3][1] = dot4(w3, i1, acc[3][1]);
            }
        }

        __syncthreads();
        // add bias, park gates in sG[32][65]
#pragma unroll
        for (int rr = 0; rr < 4; ++rr) {
            int row = 4 * tj + rr;
            int j   = ((row >> 3) << 10) + u0 + (row & 7);
            float bsum = bih[j] + bhh[j];
            sG[row * SG_STRIDE + 2 * tb]     = acc[rr][0] + bsum;
            sG[row * SG_STRIDE + 2 * tb + 1] = acc[rr][1] + bsum;
        }
        __syncthreads();

        // LSTM elementwise: 8 units x 64 batches, 2 items per thread
#pragma unroll
        for (int r = 0; r < 2; ++r) {
            int idx = tid + BLK * r;          // 0..511
            int uu  = idx >> 6;               // 0..7
            int b   = idx & 63;
            int u   = u0 + uu;
            float ig = sigm (sG[( uu     ) * SG_STRIDE + b]);
            float fg = sigm (sG[( 8 + uu ) * SG_STRIDE + b]);
            float gg = tanhf(sG[(16 + uu ) * SG_STRIDE + b]);
            float og = sigm (sG[(24 + uu ) * SG_STRIDE + b]);
            float cp = g_c[u * BB + b];
            float cn = fmaf(fg, cp, ig * gg);
            float hn = og * tanhf(cn);
            g_c[u * BB + b]    = cn;
            hwrite[b * HH + u] = hn;
        }

        bt += GRID; gridbar(bt);

        // ---------------- Phase B: s_curr = tanh(h_new @ Wenc^T + benc) -----
        {
            const float* hn = hwrite;
            int l0 = blockIdx.x * 2;
            const float4* w0 = (const float4*)(Wenc + (size_t)l0 * HH);
            const float4* w1 = (const float4*)(Wenc + (size_t)(l0 + 1) * HH);
            for (int b = warp; b < BB; b += 8) {
                const float4* hp = (const float4*)(hn + b * HH);
                float a0 = 0.f, a1 = 0.f;
#pragma unroll
                for (int it = 0; it < 8; ++it) {
                    float4 hv = __ldcg(hp + it * 32 + lane);
                    float4 wa = w0[it * 32 + lane];
                    float4 wb = w1[it * 32 + lane];
                    a0 += hv.x*wa.x + hv.y*wa.y + hv.z*wa.z + hv.w*wa.w;
                    a1 += hv.x*wb.x + hv.y*wb.y + hv.z*wb.z + hv.w*wb.w;
                }
#pragma unroll
                for (int o = 16; o; o >>= 1) {
                    a0 += __shfl_xor_sync(0xffffffffu, a0, o);
                    a1 += __shfl_xor_sync(0xffffffffu, a1, o);
                }
                if (lane == 0) {
                    float s0 = tanhf(a0 + benc[l0]);
                    float s1 = tanhf(a1 + benc[l0 + 1]);
                    g_s[b * LL + l0]     = s0;
                    g_s[b * LL + l0 + 1] = s1;
                    size_t o0 = ((size_t)b * TT + t) * LL;
                    outS[o0 + l0]     = s0;
                    outS[o0 + l0 + 1] = s1;
                }
            }
        }

        bt += GRID; gridbar(bt);

        // ---------------- Phase C: y = s@Wact^T+b ; s_pred = tanh(s@Wpred^T+b)
        // (reads only s_curr; the next writers of g_s are behind the next
        //  gridbar(A->B) of step t+1, which also orders all C reads first)
        {
            int r0 = blockIdx.x * 2;
            const float4* wa0 = (const float4*)(Wact  + (size_t)r0 * LL);
            const float4* wa1 = (const float4*)(Wact  + (size_t)(r0 + 1) * LL);
            const float4* wp0 = (const float4*)(Wpred + (size_t)r0 * LL);
            const float4* wp1 = (const float4*)(Wpred + (size_t)(r0 + 1) * LL);
            for (int b = warp; b < BB; b += 8) {
                const float4* sp = (const float4*)(g_s + b * LL);
                float y0 = 0.f, y1 = 0.f, p0 = 0.f, p1 = 0.f;
#pragma unroll
                for (int it = 0; it < 2; ++it) {
                    float4 sv = __ldcg(sp + it * 32 + lane);
                    float4 v0 = wa0[it * 32 + lane];
                    float4 v1 = wa1[it * 32 + lane];
                    float4 v2 = wp0[it * 32 + lane];
                    float4 v3 = wp1[it * 32 + lane];
                    y0 += sv.x*v0.x + sv.y*v0.y + sv.z*v0.z + sv.w*v0.w;
                    y1 += sv.x*v1.x + sv.y*v1.y + sv.z*v1.z + sv.w*v1.w;
                    p0 += sv.x*v2.x + sv.y*v2.y + sv.z*v2.z + sv.w*v2.w;
                    p1 += sv.x*v3.x + sv.y*v3.y + sv.z*v3.z + sv.w*v3.w;
                }
#pragma unroll
                for (int o = 16; o; o >>= 1) {
                    y0 += __shfl_xor_sync(0xffffffffu, y0, o);
                    y1 += __shfl_xor_sync(0xffffffffu, y1, o);
                    p0 += __shfl_xor_sync(0xffffffffu, p0, o);
                    p1 += __shfl_xor_sync(0xffffffffu, p1, o);
                }
                if (lane == 0) {
                    size_t o0 = ((size_t)b * TT + t) * OO;
                    outY[o0 + r0]     = y0 + bact[r0];
                    outY[o0 + r0 + 1] = y1 + bact[r0 + 1];
                    outP[o0 + r0]     = tanhf(p0 + bpred[r0]);
                    outP[o0 + r0 + 1] = tanhf(p1 + bpred[r0 + 1]);
                }
            }
        }
    }
}

extern "C" void kernel_launch(void* const* d_in, const int* in_sizes, int n_in,
                              void* d_out, int out_size)
{
    const float* x     = (const float*)d_in[0];   // [64,512,256]
    const float* Wih   = (const float*)d_in[1];   // [4096,512]
    const float* Whh   = (const float*)d_in[2];   // [4096,1024]
    const float* bih   = (const float*)d_in[3];   // [4096]
    const float* bhh   = (const float*)d_in[4];   // [4096]
    const float* Wenc  = (const float*)d_in[5];   // [256,1024]
    const float* benc  = (const float*)d_in[6];   // [256]
    const float* Wpred = (const float*)d_in[7];   // [256,256]
    const float* bpred = (const float*)d_in[8];   // [256]
    const float* Wact  = (const float*)d_in[9];   // [256,256]
    const float* bact  = (const float*)d_in[10];  // [256]
    float* out = (float*)d_out;                   // [y | states | preds]

    (void)in_sizes; (void)n_in; (void)out_size;

    reset_kernel<<<256, 256>>>();
    lstm_persistent<<<GRID, BLK>>>(x, Wih, Whh, bih, bhh,
                                   Wenc, benc, Wpred, bpred, Wact, bact, out);
}

// round 7
// speedup vs baseline: 1.2825x; 1.2825x over previous
#include <cuda_runtime.h>
#include <math.h>
#include <stdint.h>

// Problem dims
#define BB   64
#define TT   512
#define DD   256
#define HH   1024
#define LL   256
#define OO   256
#define KC   32
#define NCH  48          // 1536 / 32
#define GRID 256
#define BLK  256
#define NSTG 4

// Persistent state (no allocations allowed). 16B alignment is load-bearing:
// float4 and cp.async access these directly.
__device__ __align__(16) float g_h[2][BB*HH];   // double-buffered hidden, [b][u]
__device__ __align__(16) float g_c[BB*HH];      // cell state, [u][b] (CTA-private by u)
__device__ __align__(16) float g_s[BB*LL];      // latent state, [b][l]
__device__ unsigned g_count;

__global__ void reset_kernel() {
    int i = blockIdx.x * blockDim.x + threadIdx.x;
    if (i == 0) g_count = 0u;
    if (i < BB*HH) { g_h[0][i] = 0.f; g_c[i] = 0.f; }
    if (i < BB*LL) g_s[i] = 0.f;
}

__device__ __forceinline__ float sigm(float x) { return 1.f / (1.f + expf(-x)); }

__device__ __forceinline__ float dot4(float4 w, float4 v, float a) {
    a = fmaf(w.x, v.x, a);
    a = fmaf(w.y, v.y, a);
    a = fmaf(w.z, v.z, a);
    a = fmaf(w.w, v.w, a);
    return a;
}

// Grid barrier: monotonic counter, release-fence before arrive, acquire after.
__device__ __forceinline__ void gridbar(unsigned target) {
    __threadfence();
    __syncthreads();
    if (threadIdx.x == 0) {
        atomicAdd(&g_count, 1u);
        while (*((volatile unsigned*)&g_count) < target) { __nanosleep(64); }
    }
    __syncthreads();
    __threadfence();
}

__device__ __forceinline__ void cpa16(uint32_t dst, const float* src) {
    asm volatile("cp.async.cg.shared.global [%0], [%1], 16;" :: "r"(dst), "l"(src));
}
__device__ __forceinline__ void cp_commit() {
    asm volatile("cp.async.commit_group;");
}
template<int N> __device__ __forceinline__ void cp_wait() {
    asm volatile("cp.async.wait_group %0;" :: "n"(N));
}

// Stage layout (floats): W 16 rows x 32 k = 512, then I 64 b x 32 k = 2048.
// 16B-group swizzle on both: group' = kg ^ ((row>>1)&7).
#define STG_FLOATS 2560          // 512 + 2048
#define SG_STRIDE  65

__global__ void __launch_bounds__(BLK, 2)
lstm_persistent(
    const float* __restrict__ x,
    const float* __restrict__ Wih,  const float* __restrict__ Whh,
    const float* __restrict__ bih,  const float* __restrict__ bhh,
    const float* __restrict__ Wenc, const float* __restrict__ benc,
    const float* __restrict__ Wpred,const float* __restrict__ bpred,
    const float* __restrict__ Wact, const float* __restrict__ bact,
    float* __restrict__ out)
{
    __shared__ __align__(16) float stg[NSTG][STG_FLOATS];   // 40 KB

    const int tid  = threadIdx.x;
    const int lane = tid & 31;
    const int warp = tid >> 5;
    const int u0   = blockIdx.x * 4;   // 4 hidden units per CTA (16 gate rows)
    const int tj   = tid & 7;          // 8 row-pairs: rows {2tj, 2tj+1}
    const int tb   = tid >> 3;         // 32 b-pairs:  b   {2tb, 2tb+1}

    // ---- cp.async per-thread constants --------------------------------------
    // W tile: threads 0..127 carry one float4 per chunk (16 rows x 8 groups)
    const int  w_row  = tid >> 3;                       // 0..15
    const int  w_kgs  = tid & 7;                        // k-group within chunk
    const int  w_j    = ((w_row >> 2) << 10) + u0 + (w_row & 3);  // global gate row
    const float* wih_b = Wih + (size_t)w_j * 512  + w_kgs * 4;
    const float* whh_b = Whh + (size_t)w_j * 1024 + w_kgs * 4 - 512;
    const int  w_dst  = (w_row * 8 + (w_kgs ^ ((w_row >> 1) & 7))) * 4; // float off
    // I tile: every thread carries ONE pair of consecutive float4 (8 floats).
    // 256 threads x 2 float4 = 512 float4 = 64 b x 8 groups. Exact cover.
    const int  i_bb  = tid >> 2;            // batch 0..63
    const int  i_kos = (tid & 3) * 8;       // float offset of the pair within chunk
    const int  i_bg  = (tid & 3) * 2;       // first k-group of the pair
    const int  i_sw  = (i_bb >> 1) & 7;
    const int  i_d0  = 512 + i_bb * 32 + 4 * ( i_bg      ^ i_sw);
    const int  i_d1  = 512 + i_bb * 32 + 4 * ((i_bg + 1) ^ i_sw);
    const float* i_sb = g_s + i_bb * LL + i_kos - 256;

    uint32_t stg_u32 = (uint32_t)__cvta_generic_to_shared(&stg[0][0]);

    float* outY = out;
    float* outS = out + (size_t)BB * TT * OO;
    float* outP = out + (size_t)2 * BB * TT * OO;

    unsigned bt = 0;

    for (int t = 0; t < TT; ++t) {
        const float* hread  = g_h[t & 1];
        float*       hwrite = g_h[(t & 1) ^ 1];

        // t-dependent source bases for the I pair
        const float* i_xb = x + ((size_t)i_bb * TT + t) * DD + i_kos;
        const float* i_hb = hread + i_bb * HH + i_kos - 512;

        // issue one chunk's async copies into stage s
        auto issue = [&](int c, int s) {
            uint32_t sb = stg_u32 + (uint32_t)(s * STG_FLOATS * 4);
            int k0 = c * KC;
            if (tid < 128) {
                int k = k0 + w_kgs * 4;
                const float* src = (k < 512) ? (wih_b + k0) : (whh_b + k0);
                cpa16(sb + w_dst * 4, src);
            }
            {
                int k = k0 + i_kos;   // pair spans k..k+7, region-uniform per chunk
                const float* src = (k < 256) ? (i_xb + k0)
                                 : (k < 512) ? (i_sb + k0)
                                 :             (i_hb + k0);
                cpa16(sb + i_d0 * 4, src);
                cpa16(sb + i_d1 * 4, src + 4);
            }
        };

        // ---------------- Phase A: gates GEMM [16 rows x 64 b], K=1536 ------
        float acc00 = 0.f, acc01 = 0.f, acc10 = 0.f, acc11 = 0.f;

        issue(0, 0); cp_commit();
        issue(1, 1); cp_commit();
        issue(2, 2); cp_commit();

        for (int c = 0; c < NCH; ++c) {
            if (c <= 45) cp_wait<2>();
            else if (c == 46) cp_wait<1>();
            else cp_wait<0>();
            __syncthreads();
            if (c + 3 < NCH) { issue(c + 3, (c + 3) & 3); cp_commit(); }

            const float* sc = stg[c & 3];
            const float* sW = sc;
            const float* sI = sc + 512;
            const int r0 = 2 * tj, r1 = 2 * tj + 1;
            const int b0 = 2 * tb, b1 = 2 * tb + 1;
            const int swzW = tj;          // (r0>>1)&7 == (r1>>1)&7
            const int swzI = tb & 7;      // (b0>>1)&7 == (b1>>1)&7
#pragma unroll
            for (int kg = 0; kg < 8; ++kg) {
                float4 w0 = *(const float4*)&sW[r0 * 32 + 4 * (kg ^ swzW)];
                float4 w1 = *(const float4*)&sW[r1 * 32 + 4 * (kg ^ swzW)];
                float4 i0 = *(const float4*)&sI[b0 * 32 + 4 * (kg ^ swzI)];
                float4 i1 = *(const float4*)&sI[b1 * 32 + 4 * (kg ^ swzI)];
                acc00 = dot4(w0, i0, acc00);
                acc01 = dot4(w0, i1, acc01);
                acc10 = dot4(w1, i0, acc10);
                acc11 = dot4(w1, i1, acc11);
            }
        }

        __syncthreads();
        // bias + park gates in sG[16][65] (aliases stage 0; all cp.async retired)
        float* sG = stg[0];
        {
            int row = 2 * tj;
            int j0  = ((row >> 2) << 10) + u0 + (row & 3);
            float bs0 = bih[j0] + bhh[j0];
            sG[row * SG_STRIDE + 2 * tb]     = acc00 + bs0;
            sG[row * SG_STRIDE + 2 * tb + 1] = acc01 + bs0;
            int rowb = row + 1;
            int j1  = ((rowb >> 2) << 10) + u0 + (rowb & 3);
            float bs1 = bih[j1] + bhh[j1];
            sG[rowb * SG_STRIDE + 2 * tb]     = acc10 + bs1;
            sG[rowb * SG_STRIDE + 2 * tb + 1] = acc11 + bs1;
        }
        __syncthreads();

        // LSTM elementwise: 4 units x 64 batches = 256 -> 1 per thread
        {
            int uu = tid >> 6;            // 0..3
            int b  = tid & 63;
            int u  = u0 + uu;
            // gate row in sG = gate*4 + uu
            float ig = sigm (sG[( 0 + uu) * SG_STRIDE + b]);
            float fg = sigm (sG[( 4 + uu) * SG_STRIDE + b]);
            float gg = tanhf(sG[( 8 + uu) * SG_STRIDE + b]);
            float og = sigm (sG[(12 + uu) * SG_STRIDE + b]);
            float cp = g_c[u * BB + b];
            float cn = fmaf(fg, cp, ig * gg);
            float hn = og * tanhf(cn);
            g_c[u * BB + b]    = cn;
            hwrite[b * HH + u] = hn;
        }

        bt += GRID; gridbar(bt);

        // ---------------- Phase B: s_curr = tanh(h_new @ Wenc^T + benc) -----
        {
            const int l = blockIdx.x;                  // one latent row per CTA
            const float4* wl = (const float4*)(Wenc + (size_t)l * HH);
            const float bl = benc[l];
            for (int b = warp; b < BB; b += 8) {
                const float4* hp = (const float4*)(hwrite + b * HH);
                float a = 0.f;
#pragma unroll
                for (int it = 0; it < 8; ++it) {
                    float4 hv = __ldcg(hp + it * 32 + lane);
                    float4 wv = wl[it * 32 + lane];
                    a += hv.x*wv.x + hv.y*wv.y + hv.z*wv.z + hv.w*wv.w;
                }
#pragma unroll
                for (int o = 16; o; o >>= 1)
                    a += __shfl_xor_sync(0xffffffffu, a, o);
                if (lane == 0) {
                    float s = tanhf(a + bl);
                    g_s[b * LL + l] = s;
                    outS[((size_t)b * TT + t) * LL + l] = s;
                }
            }
        }

        bt += GRID; gridbar(bt);

        // ---------------- Phase C: y = s@Wact^T + b ; s_pred = tanh(s@Wpred^T + b)
        // reads only s_curr; next writers of g_s are behind the next gridbar
        {
            const int r = blockIdx.x;                  // one output row per CTA
            const float4* wa = (const float4*)(Wact  + (size_t)r * LL);
            const float4* wp = (const float4*)(Wpred + (size_t)r * LL);
            const float ba = bact[r], bp = bpred[r];
            for (int b = warp; b < BB; b += 8) {
                const float4* sp = (const float4*)(g_s + b * LL);
                float ya = 0.f, pa = 0.f;
#pragma unroll
                for (int it = 0; it < 2; ++it) {
                    float4 sv = __ldcg(sp + it * 32 + lane);
                    float4 va = wa[it * 32 + lane];
                    float4 vp = wp[it * 32 + lane];
                    ya += sv.x*va.x + sv.y*va.y + sv.z*va.z + sv.w*va.w;
                    pa += sv.x*vp.x + sv.y*vp.y + sv.z*vp.z + sv.w*vp.w;
                }
#pragma unroll
                for (int o = 16; o; o >>= 1) {
                    ya += __shfl_xor_sync(0xffffffffu, ya, o);
                    pa += __shfl_xor_sync(0xffffffffu, pa, o);
                }
                if (lane == 0) {
                    size_t o0 = ((size_t)b * TT + t) * OO;
                    outY[o0 + r] = ya + ba;
                    outP[o0 + r] = tanhf(pa + bp);
                }
            }
        }
    }
}

extern "C" void kernel_launch(void* const* d_in, const int* in_sizes, int n_in,
                              void* d_out, int out_size)
{
    const float* x     = (const float*)d_in[0];   // [64,512,256]
    const float* Wih   = (const float*)d_in[1];   // [4096,512]
    const float* Whh   = (const float*)d_in[2];   // [4096,1024]
    const float* bih   = (const float*)d_in[3];   // [4096]
    const float* bhh   = (const float*)d_in[4];   // [4096]
    const float* Wenc  = (const float*)d_in[5];   // [256,1024]
    const float* benc  = (const float*)d_in[6];   // [256]
    const float* Wpred = (const float*)d_in[7];   // [256,256]
    const float* bpred = (const float*)d_in[8];   // [256]
    const float* Wact  = (const float*)d_in[9];   // [256,256]
    const float* bact  = (const float*)d_in[10];  // [256]
    float* out = (float*)d_out;                   // [y | states | preds]

    (void)in_sizes; (void)n_in; (void)out_size;

    reset_kernel<<<256, 256>>>();
    lstm_persistent<<<GRID, BLK>>>(x, Wih, Whh, bih, bhh,
                                   Wenc, benc, Wpred, bpred, Wact, bact, out);
}

// round 9
// speedup vs baseline: 1.2834x; 1.0007x over previous
#include <cuda_runtime.h>
#include <math.h>
#include <stdint.h>

// Problem dims
#define BB   64
#define TT   512
#define DD   256
#define HH   1024
#define LL   256
#define OO   256
#define KC   32
#define NCH  48          // 1536 / 32
#define GRID 256
#define BLK  256
#define NSTG 4

// Persistent state (no allocations allowed). 16B alignment is load-bearing:
// float4 and cp.async access these directly.
__device__ __align__(16) float g_h[2][BB*HH];   // double-buffered hidden, [b][u]
__device__ __align__(16) float g_c[BB*HH];      // cell state, [u][b] (CTA-private by u)
__device__ __align__(16) float g_s[BB*LL];      // latent state, [b][l]
__device__ unsigned g_count;

__global__ void reset_kernel() {
    int i = blockIdx.x * blockDim.x + threadIdx.x;
    if (i == 0) g_count = 0u;
    if (i < BB*HH) { g_h[0][i] = 0.f; g_c[i] = 0.f; }
    if (i < BB*LL) g_s[i] = 0.f;
}

__device__ __forceinline__ float sigm(float x) { return 1.f / (1.f + expf(-x)); }

__device__ __forceinline__ float dot4(float4 w, float4 v, float a) {
    a = fmaf(w.x, v.x, a);
    a = fmaf(w.y, v.y, a);
    a = fmaf(w.z, v.z, a);
    a = fmaf(w.w, v.w, a);
    return a;
}

// Grid barrier: monotonic counter, release-fence before arrive, acquire after.
__device__ __forceinline__ void gridbar(unsigned target) {
    __threadfence();
    __syncthreads();
    if (threadIdx.x == 0) {
        atomicAdd(&g_count, 1u);
        while (*((volatile unsigned*)&g_count) < target) { __nanosleep(64); }
    }
    __syncthreads();
    __threadfence();
}

__device__ __forceinline__ void cpa16(uint32_t dst, const float* src) {
    asm volatile("cp.async.cg.shared.global [%0], [%1], 16;" :: "r"(dst), "l"(src));
}
__device__ __forceinline__ void cp_commit() {
    asm volatile("cp.async.commit_group;");
}
template<int N> __device__ __forceinline__ void cp_wait() {
    asm volatile("cp.async.wait_group %0;" :: "n"(N));
}

// Stage layout (floats): W 16 rows x 32 k = 512, then I 64 b x 32 k = 2048.
// 16B-group swizzle on both: group' = kg ^ ((row>>1)&7).
#define STG_FLOATS 2560          // 512 + 2048
#define SG_STRIDE  65

__global__ void __launch_bounds__(BLK, 2)
lstm_persistent(
    const float* __restrict__ x,
    const float* __restrict__ Wih,  const float* __restrict__ Whh,
    const float* __restrict__ bih,  const float* __restrict__ bhh,
    const float* __restrict__ Wenc, const float* __restrict__ benc,
    const float* __restrict__ Wpred,const float* __restrict__ bpred,
    const float* __restrict__ Wact, const float* __restrict__ bact,
    float* __restrict__ out)
{
    __shared__ __align__(16) float stg[NSTG][STG_FLOATS];   // 40 KB

    const int tid  = threadIdx.x;
    const int lane = tid & 31;
    const int warp = tid >> 5;
    const int u0   = blockIdx.x * 4;   // 4 hidden units per CTA (16 gate rows)
    const int tj   = tid & 7;          // 8 row-pairs: rows {2tj, 2tj+1}
    const int tb   = tid >> 3;         // 32 b-pairs:  b   {2tb, 2tb+1}

    // ---- cp.async per-thread constants --------------------------------------
    // W tile: threads 0..127 carry one float4 per chunk (16 rows x 8 groups)
    const int  w_row  = tid >> 3;                       // 0..15
    const int  w_kgs  = tid & 7;                        // k-group within chunk
    const int  w_j    = ((w_row >> 2) << 10) + u0 + (w_row & 3);  // global gate row
    const float* wih_b = Wih + (size_t)w_j * 512  + w_kgs * 4;
    const float* whh_b = Whh + (size_t)w_j * 1024 + w_kgs * 4 - 512;
    const int  w_dst  = (w_row * 8 + (w_kgs ^ ((w_row >> 1) & 7))) * 4; // float off
    // I tile: every thread carries ONE pair of consecutive float4 (8 floats).
    // 256 threads x 2 float4 = 512 float4 = 64 b x 8 groups. Exact cover.
    const int  i_bb  = tid >> 2;            // batch 0..63
    const int  i_kos = (tid & 3) * 8;       // float offset of the pair within chunk
    const int  i_bg  = (tid & 3) * 2;       // first k-group of the pair
    const int  i_sw  = (i_bb >> 1) & 7;
    const int  i_d0  = 512 + i_bb * 32 + 4 * ( i_bg      ^ i_sw);
    const int  i_d1  = 512 + i_bb * 32 + 4 * ((i_bg + 1) ^ i_sw);
    const float* i_sb = g_s + i_bb * LL + i_kos - 256;

    uint32_t stg_u32 = (uint32_t)__cvta_generic_to_shared(&stg[0][0]);

    float* outY = out;
    float* outS = out + (size_t)BB * TT * OO;
    float* outP = out + (size_t)2 * BB * TT * OO;

    unsigned bt = 0;

    for (int t = 0; t < TT; ++t) {
        const float* hread  = g_h[t & 1];
        float*       hwrite = g_h[(t & 1) ^ 1];

        // t-dependent source bases for the I pair
        const float* i_xb = x + ((size_t)i_bb * TT + t) * DD + i_kos;
        const float* i_hb = hread + i_bb * HH + i_kos - 512;

        // issue one chunk's async copies into stage s
        auto issue = [&](int c, int s) {
            uint32_t sb = stg_u32 + (uint32_t)(s * STG_FLOATS * 4);
            int k0 = c * KC;
            if (tid < 128) {
                int k = k0 + w_kgs * 4;
                const float* src = (k < 512) ? (wih_b + k0) : (whh_b + k0);
                cpa16(sb + w_dst * 4, src);
            }
            {
                int k = k0 + i_kos;   // pair spans k..k+7, region-uniform per chunk
                const float* src = (k < 256) ? (i_xb + k0)
                                 : (k < 512) ? (i_sb + k0)
                                 :             (i_hb + k0);
                cpa16(sb + i_d0 * 4, src);
                cpa16(sb + i_d1 * 4, src + 4);
            }
        };

        // ---------------- Phase A: gates GEMM [16 rows x 64 b], K=1536 ------
        float acc00 = 0.f, acc01 = 0.f, acc10 = 0.f, acc11 = 0.f;

        issue(0, 0); cp_commit();
        issue(1, 1); cp_commit();
        issue(2, 2); cp_commit();

        for (int c = 0; c < NCH; ++c) {
            if (c <= 45) cp_wait<2>();
            else if (c == 46) cp_wait<1>();
            else cp_wait<0>();
            __syncthreads();
            if (c + 3 < NCH) { issue(c + 3, (c + 3) & 3); cp_commit(); }

            const float* sc = stg[c & 3];
            const float* sW = sc;
            const float* sI = sc + 512;
            const int r0 = 2 * tj, r1 = 2 * tj + 1;
            const int b0 = 2 * tb, b1 = 2 * tb + 1;
            const int swzW = tj;          // (r0>>1)&7 == (r1>>1)&7
            const int swzI = tb & 7;      // (b0>>1)&7 == (b1>>1)&7
#pragma unroll
            for (int kg = 0; kg < 8; ++kg) {
                float4 w0 = *(const float4*)&sW[r0 * 32 + 4 * (kg ^ swzW)];
                float4 w1 = *(const float4*)&sW[r1 * 32 + 4 * (kg ^ swzW)];
                float4 i0 = *(const float4*)&sI[b0 * 32 + 4 * (kg ^ swzI)];
                float4 i1 = *(const float4*)&sI[b1 * 32 + 4 * (kg ^ swzI)];
                acc00 = dot4(w0, i0, acc00);
                acc01 = dot4(w0, i1, acc01);
                acc10 = dot4(w1, i0, acc10);
                acc11 = dot4(w1, i1, acc11);
            }
        }

        __syncthreads();
        // bias + park gates in sG[16][65] (aliases stage 0; all cp.async retired)
        float* sG = stg[0];
        {
            int row = 2 * tj;
            int j0  = ((row >> 2) << 10) + u0 + (row & 3);
            float bs0 = bih[j0] + bhh[j0];
            sG[row * SG_STRIDE + 2 * tb]     = acc00 + bs0;
            sG[row * SG_STRIDE + 2 * tb + 1] = acc01 + bs0;
            int rowb = row + 1;
            int j1  = ((rowb >> 2) << 10) + u0 + (rowb & 3);
            float bs1 = bih[j1] + bhh[j1];
            sG[rowb * SG_STRIDE + 2 * tb]     = acc10 + bs1;
            sG[rowb * SG_STRIDE + 2 * tb + 1] = acc11 + bs1;
        }
        __syncthreads();

        // LSTM elementwise: 4 units x 64 batches = 256 -> 1 per thread
        {
            int uu = tid >> 6;            // 0..3
            int b  = tid & 63;
            int u  = u0 + uu;
            // gate row in sG = gate*4 + uu
            float ig = sigm (sG[( 0 + uu) * SG_STRIDE + b]);
            float fg = sigm (sG[( 4 + uu) * SG_STRIDE + b]);
            float gg = tanhf(sG[( 8 + uu) * SG_STRIDE + b]);
            float og = sigm (sG[(12 + uu) * SG_STRIDE + b]);
            float cp = g_c[u * BB + b];
            float cn = fmaf(fg, cp, ig * gg);
            float hn = og * tanhf(cn);
            g_c[u * BB + b]    = cn;
            hwrite[b * HH + u] = hn;
        }

        bt += GRID; gridbar(bt);

        // ---------------- Phase B: s_curr = tanh(h_new @ Wenc^T + benc) -----
        {
            const int l = blockIdx.x;                  // one latent row per CTA
            const float4* wl = (const float4*)(Wenc + (size_t)l * HH);
            const float bl = benc[l];
            for (int b = warp; b < BB; b += 8) {
                const float4* hp = (const float4*)(hwrite + b * HH);
                float a = 0.f;
#pragma unroll
                for (int it = 0; it < 8; ++it) {
                    float4 hv = __ldcg(hp + it * 32 + lane);
                    float4 wv = wl[it * 32 + lane];
                    a += hv.x*wv.x + hv.y*wv.y + hv.z*wv.z + hv.w*wv.w;
                }
#pragma unroll
                for (int o = 16; o; o >>= 1)
                    a += __shfl_xor_sync(0xffffffffu, a, o);
                if (lane == 0) {
                    float s = tanhf(a + bl);
                    g_s[b * LL + l] = s;
                    outS[((size_t)b * TT + t) * LL + l] = s;
                }
            }
        }

        bt += GRID; gridbar(bt);

        // ---------------- Phase C: y = s@Wact^T + b ; s_pred = tanh(s@Wpred^T + b)
        // reads only s_curr; next writers of g_s are behind the next gridbar
        {
            const int r = blockIdx.x;                  // one output row per CTA
            const float4* wa = (const float4*)(Wact  + (size_t)r * LL);
            const float4* wp = (const float4*)(Wpred + (size_t)r * LL);
            const float ba = bact[r], bp = bpred[r];
            for (int b = warp; b < BB; b += 8) {
                const float4* sp = (const float4*)(g_s + b * LL);
                float ya = 0.f, pa = 0.f;
#pragma unroll
                for (int it = 0; it < 2; ++it) {
                    float4 sv = __ldcg(sp + it * 32 + lane);
                    float4 va = wa[it * 32 + lane];
                    float4 vp = wp[it * 32 + lane];
                    ya += sv.x*va.x + sv.y*va.y + sv.z*va.z + sv.w*va.w;
                    pa += sv.x*vp.x + sv.y*vp.y + sv.z*vp.z + sv.w*vp.w;
                }
#pragma unroll
                for (int o = 16; o; o >>= 1) {
                    ya += __shfl_xor_sync(0xffffffffu, ya, o);
                    pa += __shfl_xor_sync(0xffffffffu, pa, o);
                }
                if (lane == 0) {
                    size_t o0 = ((size_t)b * TT + t) * OO;
                    outY[o0 + r] = ya + ba;
                    outP[o0 + r] = tanhf(pa + bp);
                }
            }
        }
    }
}

extern "C" void kernel_launch(void* const* d_in, const int* in_sizes, int n_in,
                              void* d_out, int out_size)
{
    const float* x     = (const float*)d_in[0];   // [64,512,256]
    const float* Wih   = (const float*)d_in[1];   // [4096,512]
    const float* Whh   = (const float*)d_in[2];   // [4096,1024]
    const float* bih   = (const float*)d_in[3];   // [4096]
    const float* bhh   = (const float*)d_in[4];   // [4096]
    const float* Wenc  = (const float*)d_in[5];   // [256,1024]
    const float* benc  = (const float*)d_in[6];   // [256]
    const float* Wpred = (const float*)d_in[7];   // [256,256]
    const float* bpred = (const float*)d_in[8];   // [256]
    const float* Wact  = (const float*)d_in[9];   // [256,256]
    const float* bact  = (const float*)d_in[10];  // [256]
    float* out = (float*)d_out;                   // [y | states | preds]

    (void)in_sizes; (void)n_in; (void)out_size;

    reset_kernel<<<256, 256>>>();
    lstm_persistent<<<GRID, BLK>>>(x, Wih, Whh, bih, bhh,
                                   Wenc, benc, Wpred, bpred, Wact, bact, out);
}